// round 1
// baseline (speedup 1.0000x reference)
#include <cuda_runtime.h>
#include <math.h>
#include <stddef.h>

#define SEQ    2048
#define DIMM   2048
#define HEADS  16
#define DHEAD  128
#define QKVN   2304          // 2048 (q) + 128 (k) + 128 (v)
#define EPSF   1e-5f
#define MASKVF 1e-10f
#define SCALEF 0.08838834764831845f  // 128^-0.5

// ---------------- scratch (static device allocations are allowed) ----------
__device__ float g_xn[SEQ * DIMM];        // RMSNorm output
__device__ float g_wcat[DIMM * QKVN];     // [wq | wk | wv]
__device__ float g_qkv[SEQ * QKVN];       // projections (q pre-scaled)
__device__ float g_ao[SEQ * DIMM];        // attention output [n, h*d]
__device__ float g_vsuf[SEQ * DHEAD];     // suffix sums of v rows: sum_{j>i} v[j]
__device__ float g_vpart[16 * DHEAD];     // per-128-row-block partial sums of v

// ---------------- RMSNorm ---------------------------------------------------
__global__ void rmsnorm_kernel(const float* __restrict__ x,
                               const float* __restrict__ gamma) {
    int row = blockIdx.x;
    const float* xr = x + (size_t)row * DIMM;
    float ss = 0.f;
    for (int i = threadIdx.x; i < DIMM; i += 256) { float v = xr[i]; ss += v * v; }
    __shared__ float red[8];
    #pragma unroll
    for (int o = 16; o; o >>= 1) ss += __shfl_xor_sync(0xffffffffu, ss, o);
    if ((threadIdx.x & 31) == 0) red[threadIdx.x >> 5] = ss;
    __syncthreads();
    if (threadIdx.x < 32) {
        float v = (threadIdx.x < 8) ? red[threadIdx.x] : 0.f;
        #pragma unroll
        for (int o = 4; o; o >>= 1) v += __shfl_xor_sync(0xffffffffu, v, o);
        if (threadIdx.x == 0) red[0] = v;
    }
    __syncthreads();
    float inv = rsqrtf(red[0] / (float)DIMM + EPSF);
    for (int i = threadIdx.x; i < DIMM; i += 256)
        g_xn[(size_t)row * DIMM + i] = xr[i] * inv * gamma[i];
}

// ---------------- weight concat [wq | wk | wv] ------------------------------
__global__ void wcat_kernel(const float* __restrict__ wq,
                            const float* __restrict__ wk,
                            const float* __restrict__ wv) {
    int idx = blockIdx.x * 256 + threadIdx.x;
    if (idx >= DIMM * QKVN) return;
    int r = idx / QKVN, c = idx - r * QKVN;
    float v;
    if (c < DIMM)               v = wq[(size_t)r * DIMM + c];
    else if (c < DIMM + DHEAD)  v = wk[(size_t)r * DHEAD + (c - DIMM)];
    else                        v = wv[(size_t)r * DHEAD + (c - DIMM - DHEAD)];
    g_wcat[idx] = v;
}

// ---------------- fp32 SGEMM: C[M,N] = A[M,K] @ B[K,N] ----------------------
// alpha = SCALEF for output columns < scale_cols (folds q scaling into GEMM).
__global__ __launch_bounds__(256) void sgemm_kernel(
    const float* __restrict__ A, const float* __restrict__ B,
    float* __restrict__ C, int M, int N, int K, int scale_cols)
{
    __shared__ float As[8][132];   // transposed A tile, padded vs bank conflicts
    __shared__ float Bs[8][128];
    const int tid = threadIdx.x;
    const int m0 = blockIdx.y * 128, n0 = blockIdx.x * 128;
    const int arow = tid >> 1, acol = (tid & 1) << 2;
    const int brow = tid >> 5, bcol = (tid & 31) << 2;
    const int tx = tid & 15, ty = tid >> 4;

    float acc[8][8];
    #pragma unroll
    for (int i = 0; i < 8; i++)
        #pragma unroll
        for (int j = 0; j < 8; j++) acc[i][j] = 0.f;

    const float* Ap = A + (size_t)(m0 + arow) * K + acol;
    const float* Bp = B + (size_t)brow * N + n0 + bcol;

    for (int k0 = 0; k0 < K; k0 += 8) {
        float4 a = *(const float4*)Ap;
        float4 b = *(const float4*)Bp;
        As[acol + 0][arow] = a.x;
        As[acol + 1][arow] = a.y;
        As[acol + 2][arow] = a.z;
        As[acol + 3][arow] = a.w;
        *(float4*)&Bs[brow][bcol] = b;
        __syncthreads();
        #pragma unroll
        for (int k = 0; k < 8; k++) {
            float ra[8], rb[8];
            *(float4*)&ra[0] = *(const float4*)&As[k][ty * 8];
            *(float4*)&ra[4] = *(const float4*)&As[k][ty * 8 + 4];
            *(float4*)&rb[0] = *(const float4*)&Bs[k][tx * 8];
            *(float4*)&rb[4] = *(const float4*)&Bs[k][tx * 8 + 4];
            #pragma unroll
            for (int i = 0; i < 8; i++)
                #pragma unroll
                for (int j = 0; j < 8; j++)
                    acc[i][j] += ra[i] * rb[j];
        }
        __syncthreads();
        Ap += 8;
        Bp += (size_t)8 * N;
    }

    float alpha = (n0 < scale_cols) ? SCALEF : 1.0f;  // tile-uniform (2048 is a tile edge)
    #pragma unroll
    for (int i = 0; i < 8; i++) {
        float* crow = C + (size_t)(m0 + ty * 8 + i) * N + n0 + tx * 8;
        float4 v0, v1;
        v0.x = acc[i][0] * alpha; v0.y = acc[i][1] * alpha;
        v0.z = acc[i][2] * alpha; v0.w = acc[i][3] * alpha;
        v1.x = acc[i][4] * alpha; v1.y = acc[i][5] * alpha;
        v1.z = acc[i][6] * alpha; v1.w = acc[i][7] * alpha;
        *(float4*)crow = v0;
        *(float4*)(crow + 4) = v1;
    }
}

// ---------------- V suffix sums (for MASK_VALUE=1e-10 analytic tail) --------
__global__ void vpart_kernel() {
    int blk = blockIdx.x, d = threadIdx.x;
    float s = 0.f;
    #pragma unroll 8
    for (int r = 0; r < 128; r++)
        s += g_qkv[(size_t)(blk * 128 + r) * QKVN + DIMM + DHEAD + d];
    g_vpart[blk * DHEAD + d] = s;
}

__global__ void vsuf_kernel() {
    int blk = blockIdx.x, d = threadIdx.x;
    float acc = 0.f;
    for (int b = blk + 1; b < 16; b++) acc += g_vpart[b * DHEAD + d];
    #pragma unroll 4
    for (int r = 127; r >= 0; r--) {
        int row = blk * 128 + r;
        g_vsuf[(size_t)row * DHEAD + d] = acc;   // sum over j > row
        acc += g_qkv[(size_t)row * QKVN + DIMM + DHEAD + d];
    }
}

// ---------------- fp32 flash attention (64 q-rows x 64 k-cols blocks) -------
// Thread layout: 16x16; thread (ty,tx) owns S rows {4ty+r}, S cols {tx+16c},
// O cols {4tx+u, 64+4tx+u}. All smem reads are broadcast or conflict-free f4.
__global__ __launch_bounds__(256) void attn_kernel(const float* __restrict__ pos_bias) {
    extern __shared__ float smbuf[];
    float* Qs = smbuf;                 // [64][132]
    float* Ks = smbuf + 64 * 132;      // [64][132]
    float* Vs = smbuf + 2 * 64 * 132;  // [64][132]
    float* Ps = smbuf + 3 * 64 * 132;  // [64][68]

    const int h  = blockIdx.y;
    const int ib = gridDim.x - 1 - blockIdx.x;   // big blocks launch first
    const int i0 = ib * 64;
    const int tid = threadIdx.x;
    const int tx = tid & 15, ty = tid >> 4;

    // load Q tile once (already pre-scaled by SCALE in the GEMM)
    for (int t = tid; t < 64 * 32; t += 256) {
        int r = t >> 5, d4 = (t & 31) << 2;
        *(float4*)&Qs[r * 132 + d4] =
            *(const float4*)&g_qkv[(size_t)(i0 + r) * QKVN + h * DHEAD + d4];
    }

    float o[4][8];
    #pragma unroll
    for (int r = 0; r < 4; r++)
        #pragma unroll
        for (int u = 0; u < 8; u++) o[r][u] = 0.f;
    float m[4], l[4];
    #pragma unroll
    for (int r = 0; r < 4; r++) { m[r] = -1e30f; l[r] = 0.f; }

    for (int jb = 0; jb <= ib; jb++) {
        const int j0 = jb * 64;
        __syncthreads();                       // prior PV done before reload
        for (int t = tid; t < 64 * 32; t += 256) {
            int r = t >> 5, d4 = (t & 31) << 2;
            const float* src = &g_qkv[(size_t)(j0 + r) * QKVN + DIMM + d4];
            *(float4*)&Ks[r * 132 + d4] = *(const float4*)src;
            *(float4*)&Vs[r * 132 + d4] = *(const float4*)(src + DHEAD);
        }
        __syncthreads();

        // S = Q @ K^T
        float s[4][4];
        #pragma unroll
        for (int r = 0; r < 4; r++)
            #pragma unroll
            for (int c = 0; c < 4; c++) s[r][c] = 0.f;

        #pragma unroll 4
        for (int d0 = 0; d0 < DHEAD; d0 += 4) {
            float4 qv[4], kv[4];
            #pragma unroll
            for (int r = 0; r < 4; r++) qv[r] = *(const float4*)&Qs[(4 * ty + r) * 132 + d0];
            #pragma unroll
            for (int c = 0; c < 4; c++) kv[c] = *(const float4*)&Ks[(tx + 16 * c) * 132 + d0];
            #pragma unroll
            for (int r = 0; r < 4; r++)
                #pragma unroll
                for (int c = 0; c < 4; c++)
                    s[r][c] += qv[r].x * kv[c].x + qv[r].y * kv[c].y
                             + qv[r].z * kv[c].z + qv[r].w * kv[c].w;
        }

        // + pos_bias, causal exclusion inside the diagonal block (handled
        // analytically in the tail since MASK_VALUE entries live there too)
        const float* pb = pos_bias + ((size_t)h * SEQ + (size_t)(i0 + 4 * ty)) * SEQ + j0 + tx;
        #pragma unroll
        for (int r = 0; r < 4; r++) {
            const int gi = i0 + 4 * ty + r;
            #pragma unroll
            for (int c = 0; c < 4; c++) {
                float val = s[r][c] + pb[(size_t)r * SEQ + 16 * c];
                if (j0 + tx + 16 * c > gi) val = -1e30f;
                s[r][c] = val;
            }
        }

        // online softmax update
        #pragma unroll
        for (int r = 0; r < 4; r++) {
            float rmax = fmaxf(fmaxf(s[r][0], s[r][1]), fmaxf(s[r][2], s[r][3]));
            #pragma unroll
            for (int off = 8; off; off >>= 1)
                rmax = fmaxf(rmax, __shfl_xor_sync(0xffffffffu, rmax, off));
            float mn = fmaxf(m[r], rmax);
            float sc = __expf(m[r] - mn);
            float rs = 0.f;
            #pragma unroll
            for (int c = 0; c < 4; c++) { float p = __expf(s[r][c] - mn); s[r][c] = p; rs += p; }
            #pragma unroll
            for (int off = 8; off; off >>= 1)
                rs += __shfl_xor_sync(0xffffffffu, rs, off);
            l[r] = l[r] * sc + rs;
            m[r] = mn;
            #pragma unroll
            for (int u = 0; u < 8; u++) o[r][u] *= sc;
        }

        // stage P to smem for the PV GEMM
        #pragma unroll
        for (int r = 0; r < 4; r++)
            #pragma unroll
            for (int c = 0; c < 4; c++)
                Ps[(4 * ty + r) * 68 + tx + 16 * c] = s[r][c];
        __syncthreads();

        // O += P @ V
        #pragma unroll 2
        for (int jj = 0; jj < 64; jj++) {
            float pr[4];
            #pragma unroll
            for (int r = 0; r < 4; r++) pr[r] = Ps[(4 * ty + r) * 68 + jj];
            float4 va = *(const float4*)&Vs[jj * 132 + 4 * tx];
            float4 vb = *(const float4*)&Vs[jj * 132 + 64 + 4 * tx];
            #pragma unroll
            for (int r = 0; r < 4; r++) {
                o[r][0] += pr[r] * va.x; o[r][1] += pr[r] * va.y;
                o[r][2] += pr[r] * va.z; o[r][3] += pr[r] * va.w;
                o[r][4] += pr[r] * vb.x; o[r][5] += pr[r] * vb.y;
                o[r][6] += pr[r] * vb.z; o[r][7] += pr[r] * vb.w;
            }
        }
    }

    // finalize: fold in the (2047-i) masked entries, each with logit 1e-10
    #pragma unroll
    for (int r = 0; r < 4; r++) {
        const int gi = i0 + 4 * ty + r;
        float cnt = (float)(SEQ - 1 - gi);
        float mf  = fmaxf(m[r], MASKVF);
        float wu  = __expf(m[r] - mf);
        float wm  = __expf(MASKVF - mf);
        float Z   = l[r] * wu + cnt * wm;
        float invZ = 1.0f / Z;
        const float* vs = &g_vsuf[(size_t)gi * DHEAD];
        float* op = &g_ao[(size_t)gi * DIMM + h * DHEAD];
        float4 sa = *(const float4*)&vs[4 * tx];
        float4 sb = *(const float4*)&vs[64 + 4 * tx];
        float4 oa, ob;
        oa.x = (o[r][0] * wu + wm * sa.x) * invZ;
        oa.y = (o[r][1] * wu + wm * sa.y) * invZ;
        oa.z = (o[r][2] * wu + wm * sa.z) * invZ;
        oa.w = (o[r][3] * wu + wm * sa.w) * invZ;
        ob.x = (o[r][4] * wu + wm * sb.x) * invZ;
        ob.y = (o[r][5] * wu + wm * sb.y) * invZ;
        ob.z = (o[r][6] * wu + wm * sb.z) * invZ;
        ob.w = (o[r][7] * wu + wm * sb.w) * invZ;
        *(float4*)&op[4 * tx] = oa;
        *(float4*)&op[64 + 4 * tx] = ob;
    }
}

// ---------------- launch -----------------------------------------------------
extern "C" void kernel_launch(void* const* d_in, const int* in_sizes, int n_in,
                              void* d_out, int out_size) {
    (void)in_sizes; (void)n_in; (void)out_size;
    const float* x        = (const float*)d_in[0];
    const float* pos_bias = (const float*)d_in[1];
    const float* gamma    = (const float*)d_in[2];
    const float* wq       = (const float*)d_in[3];
    const float* wk       = (const float*)d_in[4];
    const float* wv       = (const float*)d_in[5];
    const float* wo       = (const float*)d_in[6];
    // d_in[7] = mask: deterministic causal tril, recomputed from indices
    float* out = (float*)d_out;

    float *xn_p, *wcat_p, *qkv_p, *ao_p;
    cudaGetSymbolAddress((void**)&xn_p,   g_xn);
    cudaGetSymbolAddress((void**)&wcat_p, g_wcat);
    cudaGetSymbolAddress((void**)&qkv_p,  g_qkv);
    cudaGetSymbolAddress((void**)&ao_p,   g_ao);

    const int ATTN_SMEM = (3 * 64 * 132 + 64 * 68) * 4;  // 118784 B
    cudaFuncSetAttribute(attn_kernel, cudaFuncAttributeMaxDynamicSharedMemorySize, ATTN_SMEM);

    wcat_kernel<<<(DIMM * QKVN + 255) / 256, 256>>>(wq, wk, wv);
    rmsnorm_kernel<<<SEQ, 256>>>(x, gamma);
    sgemm_kernel<<<dim3(QKVN / 128, SEQ / 128), 256>>>(xn_p, wcat_p, qkv_p,
                                                       SEQ, QKVN, DIMM, DIMM);
    vpart_kernel<<<16, 128>>>();
    vsuf_kernel<<<16, 128>>>();
    attn_kernel<<<dim3(32, HEADS), 256, ATTN_SMEM>>>(pos_bias);
    sgemm_kernel<<<dim3(DIMM / 128, SEQ / 128), 256>>>(ao_p, wo, out,
                                                       SEQ, DIMM, DIMM, 0);
}

// round 3
// speedup vs baseline: 1.0781x; 1.0781x over previous
#include <cuda_runtime.h>
#include <math.h>
#include <stddef.h>
#include <stdint.h>

#define SEQ    2048
#define DIMM   2048
#define HEADS  16
#define DHEAD  128
#define QKVN   2304          // 2048 (q) + 128 (k) + 128 (v)
#define EPSF   1e-5f
#define MASKVF 1e-10f
#define SCALEF 0.08838834764831845f  // 128^-0.5

// ---------------- scratch ---------------------------------------------------
__device__ float g_xn[SEQ * DIMM];          // RMSNorm output
__device__ float g_wcatT[QKVN * DIMM];      // [wq|wk|wv]^T, K-major rows (q pre-scaled)
__device__ float g_woT[DIMM * DIMM];        // wo^T, K-major rows
__device__ float g_qkv[SEQ * QKVN];         // projections (q pre-scaled)
__device__ float g_ao[SEQ * DIMM];          // attention output [n, h*d]
__device__ float g_vsuf[SEQ * DHEAD];       // suffix sums of v rows
__device__ float g_vpart[16 * DHEAD];

// ---------------- helpers ----------------------------------------------------
__device__ __forceinline__ float to_tf32(float x) {
    float r; asm("cvt.rna.tf32.f32 %0, %1;" : "=f"(r) : "f"(x)); return r;
}
__device__ __forceinline__ void cvt_hl(float x, float& h, float& l) {
    h = to_tf32(x); l = to_tf32(x - h);
}
#define MMA_TF32(Cacc, Av, Bv)                                              \
    asm volatile("mma.sync.aligned.m16n8k8.row.col.f32.tf32.tf32.f32 "      \
        "{%0,%1,%2,%3}, {%4,%5,%6,%7}, {%8,%9}, {%0,%1,%2,%3};"             \
        : "+f"((Cacc)[0]), "+f"((Cacc)[1]), "+f"((Cacc)[2]), "+f"((Cacc)[3])\
        : "r"((Av).x), "r"((Av).y), "r"((Av).z), "r"((Av).w),               \
          "r"((Bv).x), "r"((Bv).y))

// ---------------- RMSNorm ---------------------------------------------------
__global__ void rmsnorm_kernel(const float* __restrict__ x,
                               const float* __restrict__ gamma) {
    int row = blockIdx.x;
    const float* xr = x + (size_t)row * DIMM;
    float ss = 0.f;
    for (int i = threadIdx.x; i < DIMM; i += 256) { float v = xr[i]; ss += v * v; }
    __shared__ float red[8];
    #pragma unroll
    for (int o = 16; o; o >>= 1) ss += __shfl_xor_sync(0xffffffffu, ss, o);
    if ((threadIdx.x & 31) == 0) red[threadIdx.x >> 5] = ss;
    __syncthreads();
    if (threadIdx.x < 32) {
        float v = (threadIdx.x < 8) ? red[threadIdx.x] : 0.f;
        #pragma unroll
        for (int o = 4; o; o >>= 1) v += __shfl_xor_sync(0xffffffffu, v, o);
        if (threadIdx.x == 0) red[0] = v;
    }
    __syncthreads();
    float inv = rsqrtf(red[0] / (float)DIMM + EPSF);
    for (int i = threadIdx.x; i < DIMM; i += 256)
        g_xn[(size_t)row * DIMM + i] = xr[i] * inv * gamma[i];
}

// ---------------- tiled transpose: dst[C][R] = src[R][C] * scale -------------
__global__ void transpose_kernel(const float* __restrict__ src, float* __restrict__ dst,
                                 int R, int C, float scale) {
    __shared__ float tile[32][33];
    int bx = blockIdx.x * 32, by = blockIdx.y * 32;
    int tx = threadIdx.x, ty = threadIdx.y;  // 32 x 8
    #pragma unroll
    for (int j = 0; j < 32; j += 8)
        tile[ty + j][tx] = src[(size_t)(by + ty + j) * C + bx + tx];
    __syncthreads();
    #pragma unroll
    for (int j = 0; j < 32; j += 8)
        dst[(size_t)(bx + ty + j) * R + by + tx] = tile[tx][ty + j] * scale;
}

// ---------------- mma.sync tf32x3 GEMM: C[M,N] = A[M,K] @ Bt[N,K]^T ----------
// 128x128 CTA tile, 8 warps (4m x 2n, 32x64 each), K-stage 32, double-buffered
// fragment-major smem, register-pipelined global loads.
//
// smem layout per buffer (floats): Ah[32 slots][32 lanes][4] (4096),
// Al (+4096), Bh[64 slots][32 lanes][2] (+8192), Bl (+12288). 16384 f / buf.
__global__ __launch_bounds__(256) void mma_gemm_kernel(
    const float* __restrict__ A, const float* __restrict__ Bt,
    float* __restrict__ C, int M, int N, int K)
{
    extern __shared__ float sm[];
    const int tid = threadIdx.x, lane = tid & 31, warp = tid >> 5;
    const int m0 = blockIdx.y << 7, n0 = blockIdx.x << 7;
    const int wm = warp >> 1, wn = warp & 1;
    const int gid = lane >> 2, tig = lane & 3;

    float acc[2][8][4];
    #pragma unroll
    for (int mf = 0; mf < 2; mf++)
        #pragma unroll
        for (int nf = 0; nf < 8; nf++)
            #pragma unroll
            for (int q = 0; q < 4; q++) acc[mf][nf][q] = 0.f;

    float rA[4][4], rB[8][2];

    // prologue load (stage 0)
    #pragma unroll
    for (int i = 0; i < 4; i++) {
        int slot = warp + 8 * i, g = slot >> 2, k8 = slot & 3;
        const float* p = A + (size_t)(m0 + g * 16 + gid) * K + k8 * 8 + tig;
        rA[i][0] = p[0]; rA[i][1] = p[(size_t)8 * K];
        rA[i][2] = p[4]; rA[i][3] = p[(size_t)8 * K + 4];
    }
    #pragma unroll
    for (int j = 0; j < 8; j++) {
        int slot = warp + 8 * j, gg = slot >> 2, k8 = slot & 3;
        const float* p = Bt + (size_t)(n0 + gg * 8 + gid) * K + k8 * 8 + tig;
        rB[j][0] = p[0]; rB[j][1] = p[4];
    }

    const int S = K >> 5;
    for (int s = 0; s < S; s++) {
        float* buf = sm + (s & 1) * 16384;

        // convert + store fragment-major (conflict-free STS.128/STS.64)
        #pragma unroll
        for (int i = 0; i < 4; i++) {
            int slot = warp + 8 * i;
            float4 h, l;
            cvt_hl(rA[i][0], h.x, l.x); cvt_hl(rA[i][1], h.y, l.y);
            cvt_hl(rA[i][2], h.z, l.z); cvt_hl(rA[i][3], h.w, l.w);
            *(float4*)(buf + slot * 128 + lane * 4) = h;
            *(float4*)(buf + 4096 + slot * 128 + lane * 4) = l;
        }
        #pragma unroll
        for (int j = 0; j < 8; j++) {
            int slot = warp + 8 * j;
            float2 h, l;
            cvt_hl(rB[j][0], h.x, l.x); cvt_hl(rB[j][1], h.y, l.y);
            *(float2*)(buf + 8192 + slot * 64 + lane * 2) = h;
            *(float2*)(buf + 12288 + slot * 64 + lane * 2) = l;
        }
        __syncthreads();

        // prefetch next stage while MMAs run
        if (s + 1 < S) {
            const int k0 = (s + 1) << 5;
            #pragma unroll
            for (int i = 0; i < 4; i++) {
                int slot = warp + 8 * i, g = slot >> 2, k8 = slot & 3;
                const float* p = A + (size_t)(m0 + g * 16 + gid) * K + k0 + k8 * 8 + tig;
                rA[i][0] = p[0]; rA[i][1] = p[(size_t)8 * K];
                rA[i][2] = p[4]; rA[i][3] = p[(size_t)8 * K + 4];
            }
            #pragma unroll
            for (int j = 0; j < 8; j++) {
                int slot = warp + 8 * j, gg = slot >> 2, k8 = slot & 3;
                const float* p = Bt + (size_t)(n0 + gg * 8 + gid) * K + k0 + k8 * 8 + tig;
                rB[j][0] = p[0]; rB[j][1] = p[4];
            }
        }

        // consume: LDS.128/LDS.64 + 48 mma per k8
        const uint4* Ah4 = (const uint4*)(buf);
        const uint4* Al4 = (const uint4*)(buf + 4096);
        const uint2* Bh2 = (const uint2*)(buf + 8192);
        const uint2* Bl2 = (const uint2*)(buf + 12288);
        #pragma unroll
        for (int k8 = 0; k8 < 4; k8++) {
            uint4 ah[2], al[2];
            #pragma unroll
            for (int mf = 0; mf < 2; mf++) {
                int slot = (wm * 2 + mf) * 4 + k8;
                ah[mf] = Ah4[slot * 32 + lane];
                al[mf] = Al4[slot * 32 + lane];
            }
            #pragma unroll
            for (int nf = 0; nf < 8; nf++) {
                int slot = (wn * 8 + nf) * 4 + k8;
                uint2 bh = Bh2[slot * 32 + lane];
                uint2 bl = Bl2[slot * 32 + lane];
                #pragma unroll
                for (int mf = 0; mf < 2; mf++) {
                    MMA_TF32(acc[mf][nf], ah[mf], bh);
                    MMA_TF32(acc[mf][nf], ah[mf], bl);
                    MMA_TF32(acc[mf][nf], al[mf], bh);
                }
            }
        }
        __syncthreads();
    }

    // epilogue
    #pragma unroll
    for (int mf = 0; mf < 2; mf++) {
        const int r0 = m0 + wm * 32 + mf * 16 + gid;
        #pragma unroll
        for (int nf = 0; nf < 8; nf++) {
            const int c = n0 + wn * 64 + nf * 8 + tig * 2;
            float2 v0, v1;
            v0.x = acc[mf][nf][0]; v0.y = acc[mf][nf][1];
            v1.x = acc[mf][nf][2]; v1.y = acc[mf][nf][3];
            *(float2*)(C + (size_t)r0 * N + c) = v0;
            *(float2*)(C + (size_t)(r0 + 8) * N + c) = v1;
        }
    }
}

// ---------------- V suffix sums ----------------------------------------------
__global__ void vpart_kernel() {
    int blk = blockIdx.x, d = threadIdx.x;
    float s = 0.f;
    #pragma unroll 8
    for (int r = 0; r < 128; r++)
        s += g_qkv[(size_t)(blk * 128 + r) * QKVN + DIMM + DHEAD + d];
    g_vpart[blk * DHEAD + d] = s;
}

__global__ void vsuf_kernel() {
    int blk = blockIdx.x, d = threadIdx.x;
    float acc = 0.f;
    for (int b = blk + 1; b < 16; b++) acc += g_vpart[b * DHEAD + d];
    #pragma unroll 4
    for (int r = 127; r >= 0; r--) {
        int row = blk * 128 + r;
        g_vsuf[(size_t)row * DHEAD + d] = acc;
        acc += g_qkv[(size_t)row * QKVN + DIMM + DHEAD + d];
    }
}

// ---------------- fp32 flash attention (proven in R1) -------------------------
__global__ __launch_bounds__(256) void attn_kernel(const float* __restrict__ pos_bias) {
    extern __shared__ float smbuf[];
    float* Qs = smbuf;                 // [64][132]
    float* Ks = smbuf + 64 * 132;
    float* Vs = smbuf + 2 * 64 * 132;
    float* Ps = smbuf + 3 * 64 * 132;  // [64][68]

    const int h  = blockIdx.y;
    const int ib = gridDim.x - 1 - blockIdx.x;
    const int i0 = ib * 64;
    const int tid = threadIdx.x;
    const int tx = tid & 15, ty = tid >> 4;

    for (int t = tid; t < 64 * 32; t += 256) {
        int r = t >> 5, d4 = (t & 31) << 2;
        *(float4*)&Qs[r * 132 + d4] =
            *(const float4*)&g_qkv[(size_t)(i0 + r) * QKVN + h * DHEAD + d4];
    }

    float o[4][8];
    #pragma unroll
    for (int r = 0; r < 4; r++)
        #pragma unroll
        for (int u = 0; u < 8; u++) o[r][u] = 0.f;
    float m[4], l[4];
    #pragma unroll
    for (int r = 0; r < 4; r++) { m[r] = -1e30f; l[r] = 0.f; }

    for (int jb = 0; jb <= ib; jb++) {
        const int j0 = jb * 64;
        __syncthreads();
        for (int t = tid; t < 64 * 32; t += 256) {
            int r = t >> 5, d4 = (t & 31) << 2;
            const float* src = &g_qkv[(size_t)(j0 + r) * QKVN + DIMM + d4];
            *(float4*)&Ks[r * 132 + d4] = *(const float4*)src;
            *(float4*)&Vs[r * 132 + d4] = *(const float4*)(src + DHEAD);
        }
        __syncthreads();

        float s[4][4];
        #pragma unroll
        for (int r = 0; r < 4; r++)
            #pragma unroll
            for (int c = 0; c < 4; c++) s[r][c] = 0.f;

        #pragma unroll 4
        for (int d0 = 0; d0 < DHEAD; d0 += 4) {
            float4 qv[4], kv[4];
            #pragma unroll
            for (int r = 0; r < 4; r++) qv[r] = *(const float4*)&Qs[(4 * ty + r) * 132 + d0];
            #pragma unroll
            for (int c = 0; c < 4; c++) kv[c] = *(const float4*)&Ks[(tx + 16 * c) * 132 + d0];
            #pragma unroll
            for (int r = 0; r < 4; r++)
                #pragma unroll
                for (int c = 0; c < 4; c++)
                    s[r][c] += qv[r].x * kv[c].x + qv[r].y * kv[c].y
                             + qv[r].z * kv[c].z + qv[r].w * kv[c].w;
        }

        const float* pb = pos_bias + ((size_t)h * SEQ + (size_t)(i0 + 4 * ty)) * SEQ + j0 + tx;
        #pragma unroll
        for (int r = 0; r < 4; r++) {
            const int gi = i0 + 4 * ty + r;
            #pragma unroll
            for (int c = 0; c < 4; c++) {
                float val = s[r][c] + pb[(size_t)r * SEQ + 16 * c];
                if (j0 + tx + 16 * c > gi) val = -1e30f;
                s[r][c] = val;
            }
        }

        #pragma unroll
        for (int r = 0; r < 4; r++) {
            float rmax = fmaxf(fmaxf(s[r][0], s[r][1]), fmaxf(s[r][2], s[r][3]));
            #pragma unroll
            for (int off = 8; off; off >>= 1)
                rmax = fmaxf(rmax, __shfl_xor_sync(0xffffffffu, rmax, off));
            float mn = fmaxf(m[r], rmax);
            float sc = __expf(m[r] - mn);
            float rs = 0.f;
            #pragma unroll
            for (int c = 0; c < 4; c++) { float p = __expf(s[r][c] - mn); s[r][c] = p; rs += p; }
            #pragma unroll
            for (int off = 8; off; off >>= 1)
                rs += __shfl_xor_sync(0xffffffffu, rs, off);
            l[r] = l[r] * sc + rs;
            m[r] = mn;
            #pragma unroll
            for (int u = 0; u < 8; u++) o[r][u] *= sc;
        }

        #pragma unroll
        for (int r = 0; r < 4; r++)
            #pragma unroll
            for (int c = 0; c < 4; c++)
                Ps[(4 * ty + r) * 68 + tx + 16 * c] = s[r][c];
        __syncthreads();

        #pragma unroll 2
        for (int jj = 0; jj < 64; jj++) {
            float pr[4];
            #pragma unroll
            for (int r = 0; r < 4; r++) pr[r] = Ps[(4 * ty + r) * 68 + jj];
            float4 va = *(const float4*)&Vs[jj * 132 + 4 * tx];
            float4 vb = *(const float4*)&Vs[jj * 132 + 64 + 4 * tx];
            #pragma unroll
            for (int r = 0; r < 4; r++) {
                o[r][0] += pr[r] * va.x; o[r][1] += pr[r] * va.y;
                o[r][2] += pr[r] * va.z; o[r][3] += pr[r] * va.w;
                o[r][4] += pr[r] * vb.x; o[r][5] += pr[r] * vb.y;
                o[r][6] += pr[r] * vb.z; o[r][7] += pr[r] * vb.w;
            }
        }
    }

    #pragma unroll
    for (int r = 0; r < 4; r++) {
        const int gi = i0 + 4 * ty + r;
        float cnt = (float)(SEQ - 1 - gi);
        float mf  = fmaxf(m[r], MASKVF);
        float wu  = __expf(m[r] - mf);
        float wm  = __expf(MASKVF - mf);
        float Z   = l[r] * wu + cnt * wm;
        float invZ = 1.0f / Z;
        const float* vs = &g_vsuf[(size_t)gi * DHEAD];
        float* op = &g_ao[(size_t)gi * DIMM + h * DHEAD];
        float4 sa = *(const float4*)&vs[4 * tx];
        float4 sb = *(const float4*)&vs[64 + 4 * tx];
        float4 oa, ob;
        oa.x = (o[r][0] * wu + wm * sa.x) * invZ;
        oa.y = (o[r][1] * wu + wm * sa.y) * invZ;
        oa.z = (o[r][2] * wu + wm * sa.z) * invZ;
        oa.w = (o[r][3] * wu + wm * sa.w) * invZ;
        ob.x = (o[r][4] * wu + wm * sb.x) * invZ;
        ob.y = (o[r][5] * wu + wm * sb.y) * invZ;
        ob.z = (o[r][6] * wu + wm * sb.z) * invZ;
        ob.w = (o[r][7] * wu + wm * sb.w) * invZ;
        *(float4*)&op[4 * tx] = oa;
        *(float4*)&op[64 + 4 * tx] = ob;
    }
}

// ---------------- launch -------------------------------------------------------
extern "C" void kernel_launch(void* const* d_in, const int* in_sizes, int n_in,
                              void* d_out, int out_size) {
    (void)in_sizes; (void)n_in; (void)out_size;
    const float* x        = (const float*)d_in[0];
    const float* pos_bias = (const float*)d_in[1];
    const float* gamma    = (const float*)d_in[2];
    const float* wq       = (const float*)d_in[3];
    const float* wk       = (const float*)d_in[4];
    const float* wv       = (const float*)d_in[5];
    const float* wo       = (const float*)d_in[6];
    float* out = (float*)d_out;

    float *xn_p, *wcatT_p, *woT_p, *qkv_p, *ao_p;
    cudaGetSymbolAddress((void**)&xn_p,    g_xn);
    cudaGetSymbolAddress((void**)&wcatT_p, g_wcatT);
    cudaGetSymbolAddress((void**)&woT_p,   g_woT);
    cudaGetSymbolAddress((void**)&qkv_p,   g_qkv);
    cudaGetSymbolAddress((void**)&ao_p,    g_ao);

    const int ATTN_SMEM = (3 * 64 * 132 + 64 * 68) * 4;   // 118784 B
    const int MMA_SMEM  = 2 * 16384 * 4;                  // 131072 B
    cudaFuncSetAttribute(attn_kernel, cudaFuncAttributeMaxDynamicSharedMemorySize, ATTN_SMEM);
    cudaFuncSetAttribute(mma_gemm_kernel, cudaFuncAttributeMaxDynamicSharedMemorySize, MMA_SMEM);

    dim3 tb(32, 8);
    // weight transposes (Q scale folded into wq^T)
    transpose_kernel<<<dim3(DIMM / 32, DIMM / 32), tb>>>(wq, wcatT_p, DIMM, DIMM, SCALEF);
    transpose_kernel<<<dim3(DHEAD / 32, DIMM / 32), tb>>>(wk, wcatT_p + (size_t)2048 * DIMM, DIMM, DHEAD, 1.0f);
    transpose_kernel<<<dim3(DHEAD / 32, DIMM / 32), tb>>>(wv, wcatT_p + (size_t)2176 * DIMM, DIMM, DHEAD, 1.0f);
    transpose_kernel<<<dim3(DIMM / 32, DIMM / 32), tb>>>(wo, woT_p, DIMM, DIMM, 1.0f);

    rmsnorm_kernel<<<SEQ, 256>>>(x, gamma);

    mma_gemm_kernel<<<dim3(QKVN / 128, SEQ / 128), 256, MMA_SMEM>>>(
        xn_p, wcatT_p, qkv_p, SEQ, QKVN, DIMM);

    vpart_kernel<<<16, 128>>>();
    vsuf_kernel<<<16, 128>>>();
    attn_kernel<<<dim3(32, HEADS), 256, ATTN_SMEM>>>(pos_bias);

    mma_gemm_kernel<<<dim3(DIMM / 128, SEQ / 128), 256, MMA_SMEM>>>(
        ao_p, woT_p, out, SEQ, DIMM, DIMM);
}